// round 8
// baseline (speedup 1.0000x reference)
#include <cuda_runtime.h>

typedef unsigned long long ull;

#define S_LEN 2048
#define COLS 1024

__device__ float g_xg[(size_t)32 * S_LEN * COLS];   // [b*S+s][gate*256+j], gates f,i,c,o
__device__ float g_h[2][32][256];                   // double-buffered hidden state
__device__ unsigned int g_flag[2][4][32];           // [half][group][cta] step flags

__device__ __forceinline__ ull fma2(ull a, ull b, ull c){
  ull d; asm("fma.rn.f32x2 %0, %1, %2, %3;" : "=l"(d) : "l"(a), "l"(b), "l"(c)); return d;
}
__device__ __forceinline__ ull dup2(float x){
  ull d; asm("mov.b64 %0, {%1, %1};" : "=l"(d) : "f"(x)); return d;
}
__device__ __forceinline__ void unpack2(ull v, float& lo, float& hi){
  asm("mov.b64 {%0, %1}, %2;" : "=f"(lo), "=f"(hi) : "l"(v));
}
__device__ __forceinline__ float sigmoidf_(float x){ return 1.f / (1.f + __expf(-x)); }

__global__ void init_state(){
  int tid = blockIdx.x * blockDim.x + threadIdx.x;
  float* hz = (float*)g_h;
  if (tid < 2 * 32 * 256) hz[tid] = 0.f;
  if (tid < 256) ((unsigned int*)g_flag)[tid] = 0u;
}

// ---------------- kernel 1: xg = x @ W + b (fp32x2 GEMM, 128x64x32 tiles) ----------------
__global__ __launch_bounds__(256, 2) void xw_gemm(
    const float* __restrict__ x,
    const float* __restrict__ Wf, const float* __restrict__ Wi,
    const float* __restrict__ Wc, const float* __restrict__ Wo,
    const float* __restrict__ bf, const float* __restrict__ bi,
    const float* __restrict__ bc, const float* __restrict__ bo)
{
  __shared__ float A_s[32][132];
  __shared__ float B_s[32][68];
  const int r0 = blockIdx.x * 128;
  const int c0 = blockIdx.y * 64;
  const int gate = c0 >> 8, j0 = c0 & 255;
  const float* Wg; const float* bg;
  if (gate == 0){ Wg = Wf; bg = bf; } else if (gate == 1){ Wg = Wi; bg = bi; }
  else if (gate == 2){ Wg = Wc; bg = bc; } else { Wg = Wo; bg = bo; }

  const int tid = threadIdx.x;
  const int tx = tid & 15, ty = tid >> 4;
  const int arow = tid >> 3, ak = (tid & 7) * 4;

  ull acc[4][4];
  #pragma unroll
  for (int i = 0; i < 4; i++)
    #pragma unroll
    for (int j = 0; j < 4; j++) acc[i][j] = 0ull;

  for (int kc = 0; kc < 256; kc += 32){
    #pragma unroll
    for (int i = 0; i < 4; i++){
      float4 v = *(const float4*)&x[(size_t)(r0 + arow + i*32) * 256 + kc + ak];
      A_s[ak+0][arow + i*32] = v.x; A_s[ak+1][arow + i*32] = v.y;
      A_s[ak+2][arow + i*32] = v.z; A_s[ak+3][arow + i*32] = v.w;
    }
    #pragma unroll
    for (int j = 0; j < 2; j++){
      int e = tid + j*256, kk = e >> 4, nn = (e & 15) * 4;
      *(float4*)&B_s[kk][nn] = *(const float4*)&Wg[(size_t)(kc + kk) * 256 + j0 + nn];
    }
    __syncthreads();
    #pragma unroll
    for (int k = 0; k < 32; k++){
      ulonglong2 a01 = *(const ulonglong2*)&A_s[k][ty*8];
      ulonglong2 a23 = *(const ulonglong2*)&A_s[k][ty*8 + 4];
      float4 bq = *(const float4*)&B_s[k][tx*4];
      ull bb0 = dup2(bq.x), bb1 = dup2(bq.y), bb2 = dup2(bq.z), bb3 = dup2(bq.w);
      ull av[4] = {a01.x, a01.y, a23.x, a23.y};
      #pragma unroll
      for (int i = 0; i < 4; i++){
        acc[i][0] = fma2(av[i], bb0, acc[i][0]);
        acc[i][1] = fma2(av[i], bb1, acc[i][1]);
        acc[i][2] = fma2(av[i], bb2, acc[i][2]);
        acc[i][3] = fma2(av[i], bb3, acc[i][3]);
      }
    }
    __syncthreads();
  }

  float bias[4];
  #pragma unroll
  for (int j = 0; j < 4; j++) bias[j] = bg[j0 + tx*4 + j];
  #pragma unroll
  for (int i = 0; i < 4; i++){
    float lo[4], hi[4];
    #pragma unroll
    for (int j = 0; j < 4; j++) unpack2(acc[i][j], lo[j], hi[j]);
    size_t base = (size_t)(r0 + ty*8 + 2*i) * COLS + c0 + tx*4;
    *(float4*)&g_xg[base]        = make_float4(lo[0]+bias[0], lo[1]+bias[1], lo[2]+bias[2], lo[3]+bias[3]);
    *(float4*)&g_xg[base + COLS] = make_float4(hi[0]+bias[0], hi[1]+bias[1], hi[2]+bias[2], hi[3]+bias[3]);
  }
}

// ---------------- kernel 2: persistent recurrence ----------------
// 128 CTAs = 4 groups (8 batches) x 32 CTAs (8 units x 4 gates = 32 cols). 1 CTA/SM.
// Warp w owns cols 4w..4w+3 over ALL 256 k; U lives in registers; butterfly fold.
__global__ __launch_bounds__(256, 1) void lstm_rec(
    const float* __restrict__ Uf, const float* __restrict__ Ui,
    const float* __restrict__ Uc, const float* __restrict__ Uo,
    float* __restrict__ out, int out_size)
{
  __shared__ float U_s[32][256];   // staging only (32KB)
  __shared__ float h_s[8][256];    // 8KB
  __shared__ float hsum[32][9];    // [col][b]

  const int tid = threadIdx.x;
  const int w = tid >> 5, lane = tid & 31;
  const int cta = blockIdx.x, grp = cta >> 5, m = cta & 31;
  const int j0 = m * 8;

  // stage U slice: col c = gate*8 + unit
  for (int e = tid; e < 32 * 256; e += 256){
    int c = e & 31, k = e >> 5;
    int g = c >> 3, u = c & 7;
    const float* Ug = (g == 0) ? Uf : (g == 1) ? Ui : (g == 2) ? Uc : Uo;
    U_s[c][k] = Ug[k * 256 + j0 + u];
  }
  __syncthreads();

  // persistent U registers: 4 cols x (k chunks [lane*4, +4) and [128+lane*4, +4))
  ulonglong2 uA[4], uB[4];
  #pragma unroll
  for (int c = 0; c < 4; c++){
    uA[c] = *(const ulonglong2*)&U_s[w*4 + c][lane*4];
    uB[c] = *(const ulonglong2*)&U_s[w*4 + c][128 + lane*4];
  }

  const int bb = tid >> 3, uu = tid & 7;   // gate-thread mapping (tid < 64)
  const int gb = grp * 8 + bb;
  const int half = (tid >> 5) & 1;         // gate warp half (0: b0-3, 1: b4-7)
  float cst = 0.f, hlast = 0.f;

  for (int s = 0; s < S_LEN; s++){
    const int p = s & 1, pn = p ^ 1;

    // xg prefetch (consumed ~1500 cyc later at gate phase)
    float xg0, xg1, xg2, xg3;
    if (tid < 64){
      const float* xp = &g_xg[((size_t)gb * S_LEN + s) * COLS + j0 + uu];
      xg0 = __ldg(xp); xg1 = __ldg(xp + 256); xg2 = __ldg(xp + 512); xg3 = __ldg(xp + 768);
    }
    // cooperative h load: 2048 floats
    {
      int b = tid >> 5, k8 = (tid & 31) * 8;
      float4 v0 = *(const float4*)&g_h[p][grp*8 + b][k8];
      float4 v1 = *(const float4*)&g_h[p][grp*8 + b][k8 + 4];
      *(float4*)&h_s[b][k8]     = v0;
      *(float4*)&h_s[b][k8 + 4] = v1;
    }
    __syncthreads();

    // matvec: acc[c*8+b], conflict-free LDS.128 on h
    ull a2[32];
    #pragma unroll
    for (int i = 0; i < 32; i++) a2[i] = 0ull;
    #pragma unroll
    for (int b = 0; b < 8; b++){
      ulonglong2 hA = *(const ulonglong2*)&h_s[b][lane*4];
      ulonglong2 hB = *(const ulonglong2*)&h_s[b][128 + lane*4];
      #pragma unroll
      for (int c = 0; c < 4; c++){
        ull acc = a2[c*8 + b];
        acc = fma2(hA.x, uA[c].x, acc);
        acc = fma2(hA.y, uA[c].y, acc);
        acc = fma2(hB.x, uB[c].x, acc);
        acc = fma2(hB.y, uB[c].y, acc);
        a2[c*8 + b] = acc;
      }
    }
    // unpack + in-warp butterfly fold: lane L ends with sum for (c=L>>3, b=L&7)
    float v[32];
    #pragma unroll
    for (int i = 0; i < 32; i++){ float lo, hi; unpack2(a2[i], lo, hi); v[i] = lo + hi; }
    #pragma unroll
    for (int off = 16; off >= 1; off >>= 1){
      const bool hib = (lane & off) != 0;
      #pragma unroll
      for (int i = 0; i < off; i++){
        float a = v[i], b = v[i + off];
        float send = hib ? a : b;
        float recv = __shfl_xor_sync(0xffffffffu, send, off);
        v[i] = (hib ? b : a) + recv;
      }
    }
    hsum[w*4 + (lane >> 3)][lane & 7] = v[0];
    __syncthreads();

    // gates: threads 0..63 = (batch bb, unit uu); warp0 b0-3, warp1 b4-7
    if (tid < 64){
      float f  = sigmoidf_(xg0 + hsum[uu][bb]);
      float ii = sigmoidf_(xg1 + hsum[8 + uu][bb]);
      float gg = tanhf(xg2 + hsum[16 + uu][bb]);
      float oo = sigmoidf_(xg3 + hsum[24 + uu][bb]);
      cst = f * cst + ii * gg;
      hlast = oo * tanhf(cst);
      g_h[pn][gb][j0 + uu] = hlast;
      out[((size_t)gb * S_LEN + s) * 256 + j0 + uu] = hlast;
      __syncwarp();
      if ((tid & 31) == 0){
        __threadfence();
        asm volatile("st.relaxed.gpu.u32 [%0], %1;"
                     :: "l"(&g_flag[half][grp][m]), "r"((unsigned)(s + 1)));
      }
      // coalesced uncontended poll: lane L watches CTA L's flag of this half
      unsigned vfl, target = (unsigned)(s + 1);
      do {
        asm volatile("ld.acquire.gpu.u32 %0, [%1];"
                     : "=r"(vfl) : "l"(&g_flag[half][grp][tid & 31]));
      } while (__any_sync(0xffffffffu, vfl < target));
    }
    __syncthreads();
  }

  // final (h_T, c_T), appended after hidden_seq if the output carries them
  if (tid < 64 && out_size >= 16777216 + 16384){
    size_t base = (size_t)16777216 + (size_t)gb * 256 + j0 + uu;
    out[base]        = hlast;
    out[base + 8192] = cst;
  }
}

extern "C" void kernel_launch(void* const* d_in, const int* in_sizes, int n_in,
                              void* d_out, int out_size) {
  const float* x  = (const float*)d_in[0];
  const float* Wf = (const float*)d_in[1];
  const float* Uf = (const float*)d_in[2];
  const float* bf = (const float*)d_in[3];
  const float* Wi = (const float*)d_in[4];
  const float* Ui = (const float*)d_in[5];
  const float* bi = (const float*)d_in[6];
  const float* Wo = (const float*)d_in[7];
  const float* Uo = (const float*)d_in[8];
  const float* bo = (const float*)d_in[9];
  const float* Wc = (const float*)d_in[10];
  const float* Uc = (const float*)d_in[11];
  const float* bc = (const float*)d_in[12];
  float* out = (float*)d_out;

  init_state<<<64, 256>>>();
  dim3 g1(512, 16);
  xw_gemm<<<g1, 256>>>(x, Wf, Wi, Wc, Wo, bf, bi, bc, bo);
  lstm_rec<<<128, 256>>>(Uf, Ui, Uc, Uo, out, out_size);
}

// round 9
// speedup vs baseline: 1.9800x; 1.9800x over previous
#include <cuda_runtime.h>

typedef unsigned long long ull;

#define S_LEN 2048
#define COLS 1024
#define KPAD 260
#define HPAD 264

__device__ float g_xg[(size_t)32 * S_LEN * COLS];   // [b*S+s][gate*256+j], gates f,i,c,o
__device__ float g_h[2][32][256];                   // double-buffered hidden state
__device__ unsigned int g_flag[4][32];              // per-group, per-CTA step flags

__device__ __forceinline__ ull fma2(ull a, ull b, ull c){
  ull d; asm("fma.rn.f32x2 %0, %1, %2, %3;" : "=l"(d) : "l"(a), "l"(b), "l"(c)); return d;
}
__device__ __forceinline__ ull dup2(float x){
  ull d; asm("mov.b64 %0, {%1, %1};" : "=l"(d) : "f"(x)); return d;
}
__device__ __forceinline__ void unpack2(ull v, float& lo, float& hi){
  asm("mov.b64 {%0, %1}, %2;" : "=f"(lo), "=f"(hi) : "l"(v));
}
__device__ __forceinline__ float sigmoidf_(float x){ return 1.f / (1.f + __expf(-x)); }

__global__ void init_state(){
  int tid = blockIdx.x * blockDim.x + threadIdx.x;
  float* hz = (float*)g_h;
  if (tid < 2 * 32 * 256) hz[tid] = 0.f;
  if (tid < 128) ((unsigned int*)g_flag)[tid] = 0u;
}

// ---------------- kernel 1: xg = x @ W + b (fp32x2 GEMM, 128x64x32 tiles) ----------------
__global__ __launch_bounds__(256, 2) void xw_gemm(
    const float* __restrict__ x,
    const float* __restrict__ Wf, const float* __restrict__ Wi,
    const float* __restrict__ Wc, const float* __restrict__ Wo,
    const float* __restrict__ bf, const float* __restrict__ bi,
    const float* __restrict__ bc, const float* __restrict__ bo)
{
  __shared__ float A_s[32][132];
  __shared__ float B_s[32][68];
  const int r0 = blockIdx.x * 128;
  const int c0 = blockIdx.y * 64;
  const int gate = c0 >> 8, j0 = c0 & 255;
  const float* Wg; const float* bg;
  if (gate == 0){ Wg = Wf; bg = bf; } else if (gate == 1){ Wg = Wi; bg = bi; }
  else if (gate == 2){ Wg = Wc; bg = bc; } else { Wg = Wo; bg = bo; }

  const int tid = threadIdx.x;
  const int tx = tid & 15, ty = tid >> 4;
  const int arow = tid >> 3, ak = (tid & 7) * 4;

  ull acc[4][4];
  #pragma unroll
  for (int i = 0; i < 4; i++)
    #pragma unroll
    for (int j = 0; j < 4; j++) acc[i][j] = 0ull;

  for (int kc = 0; kc < 256; kc += 32){
    #pragma unroll
    for (int i = 0; i < 4; i++){
      float4 v = *(const float4*)&x[(size_t)(r0 + arow + i*32) * 256 + kc + ak];
      A_s[ak+0][arow + i*32] = v.x; A_s[ak+1][arow + i*32] = v.y;
      A_s[ak+2][arow + i*32] = v.z; A_s[ak+3][arow + i*32] = v.w;
    }
    #pragma unroll
    for (int j = 0; j < 2; j++){
      int e = tid + j*256, kk = e >> 4, nn = (e & 15) * 4;
      *(float4*)&B_s[kk][nn] = *(const float4*)&Wg[(size_t)(kc + kk) * 256 + j0 + nn];
    }
    __syncthreads();
    #pragma unroll
    for (int k = 0; k < 32; k++){
      ulonglong2 a01 = *(const ulonglong2*)&A_s[k][ty*8];
      ulonglong2 a23 = *(const ulonglong2*)&A_s[k][ty*8 + 4];
      float4 bq = *(const float4*)&B_s[k][tx*4];
      ull bb0 = dup2(bq.x), bb1 = dup2(bq.y), bb2 = dup2(bq.z), bb3 = dup2(bq.w);
      ull av[4] = {a01.x, a01.y, a23.x, a23.y};
      #pragma unroll
      for (int i = 0; i < 4; i++){
        acc[i][0] = fma2(av[i], bb0, acc[i][0]);
        acc[i][1] = fma2(av[i], bb1, acc[i][1]);
        acc[i][2] = fma2(av[i], bb2, acc[i][2]);
        acc[i][3] = fma2(av[i], bb3, acc[i][3]);
      }
    }
    __syncthreads();
  }

  float bias[4];
  #pragma unroll
  for (int j = 0; j < 4; j++) bias[j] = bg[j0 + tx*4 + j];
  #pragma unroll
  for (int i = 0; i < 4; i++){
    float lo[4], hi[4];
    #pragma unroll
    for (int j = 0; j < 4; j++) unpack2(acc[i][j], lo[j], hi[j]);
    size_t base = (size_t)(r0 + ty*8 + 2*i) * COLS + c0 + tx*4;
    *(float4*)&g_xg[base]        = make_float4(lo[0]+bias[0], lo[1]+bias[1], lo[2]+bias[2], lo[3]+bias[3]);
    *(float4*)&g_xg[base + COLS] = make_float4(hi[0]+bias[0], hi[1]+bias[1], hi[2]+bias[2], hi[3]+bias[3]);
  }
}

// ---------------- kernel 2: persistent recurrence (R4 layout) ----------------
// 128 CTAs = 4 groups (8 batches) x 32 CTAs (8 units x 4 gates = 32 cols). 1 CTA/SM.
// warp = k-slice (32 k), lane = col. U register-resident; h broadcast from smem.
__global__ __launch_bounds__(256, 1) void lstm_rec(
    const float* __restrict__ Uf, const float* __restrict__ Ui,
    const float* __restrict__ Uc, const float* __restrict__ Uo,
    float* __restrict__ out, int out_size)
{
  __shared__ float U_s[32][KPAD];   // staging for register hoist
  __shared__ float h_s[8][HPAD];
  __shared__ float red[8 * 288];    // [k-slice][col*9 + b]

  const int tid = threadIdx.x;
  const int w = tid >> 5, lane = tid & 31;
  const int cta = blockIdx.x, grp = cta >> 5, m = cta & 31;
  const int j0 = m * 8;

  // stage U slice: col c = gate*8 + unit
  for (int e = tid; e < 32 * 256; e += 256){
    int c = e & 31, k = e >> 5;
    int g = c >> 3, u = c & 7;
    const float* Ug = (g == 0) ? Uf : (g == 1) ? Ui : (g == 2) ? Uc : Uo;
    U_s[c][k] = Ug[k * 256 + j0 + u];
  }
  __syncthreads();

  // hoist this thread's U chunk: col=lane, k in [w*32, w*32+32) -> 16 ull
  const int kb = w * 32;
  ulonglong2 ur[8];
  #pragma unroll
  for (int jj = 0; jj < 8; jj++)
    ur[jj] = *(const ulonglong2*)&U_s[lane][kb + jj*4];

  const int bb = tid >> 3, uu = tid & 7;   // gate-thread mapping (tid < 64)
  const int gb = grp * 8 + bb;
  float cst = 0.f, hlast = 0.f;

  for (int s = 0; s < S_LEN; s++){
    const int p = s & 1, pn = p ^ 1;

    // xg prefetch (DRAM, consumed ~1000+ cyc later at gate phase)
    float xg0, xg1, xg2, xg3;
    if (tid < 64){
      const float* xp = &g_xg[((size_t)gb * S_LEN + s) * COLS + j0 + uu];
      xg0 = __ldg(xp); xg1 = __ldg(xp + 256); xg2 = __ldg(xp + 512); xg3 = __ldg(xp + 768);
    }
    // cooperative h load: 2048 floats from L2
    {
      int b = tid >> 5, k8 = (tid & 31) * 8;
      float4 v0 = *(const float4*)&g_h[p][grp*8 + b][k8];
      float4 v1 = *(const float4*)&g_h[p][grp*8 + b][k8 + 4];
      *(float4*)&h_s[b][k8]     = v0;
      *(float4*)&h_s[b][k8 + 4] = v1;
    }
    __syncthreads();

    // matvec partials: thread = (k-slice w, col lane), 8 batch accumulators.
    // h loads are warp-uniform (broadcast); U is in registers.
    ull acc2[8];
    #pragma unroll
    for (int b = 0; b < 8; b++) acc2[b] = 0ull;
    #pragma unroll
    for (int jj = 0; jj < 8; jj++){
      const ulonglong2 uv = ur[jj];
      #pragma unroll
      for (int b = 0; b < 8; b++){
        ulonglong2 hv = *(const ulonglong2*)&h_s[b][kb + jj*4];
        acc2[b] = fma2(hv.x, uv.x, acc2[b]);
        acc2[b] = fma2(hv.y, uv.y, acc2[b]);
      }
    }
    #pragma unroll
    for (int b = 0; b < 8; b++){
      float lo, hi; unpack2(acc2[b], lo, hi);
      red[w*288 + lane*9 + b] = lo + hi;
    }
    __syncthreads();

    // gates: threads 0..63 = (batch bb, unit uu)
    if (tid < 64){
      float z0 = xg0, z1 = xg1, z2 = xg2, z3 = xg3;
      #pragma unroll
      for (int ks = 0; ks < 8; ks++){
        z0 += red[ks*288 + (0*8 + uu)*9 + bb];
        z1 += red[ks*288 + (1*8 + uu)*9 + bb];
        z2 += red[ks*288 + (2*8 + uu)*9 + bb];
        z3 += red[ks*288 + (3*8 + uu)*9 + bb];
      }
      float f  = sigmoidf_(z0);
      float ii = sigmoidf_(z1);
      float gg = tanhf(z2);
      float oo = sigmoidf_(z3);
      cst = f * cst + ii * gg;
      hlast = oo * tanhf(cst);
      g_h[pn][gb][j0 + uu] = hlast;
    }
    __syncthreads();
    if (tid == 0){
      __threadfence();
      asm volatile("st.relaxed.gpu.u32 [%0], %1;"
                   :: "l"(&g_flag[grp][m]), "r"((unsigned)(s + 1)));
    }
    // out store overlaps the poll window (no ordering needed)
    if (tid < 64)
      out[((size_t)gb * S_LEN + s) * 256 + j0 + uu] = hlast;
    // coalesced uncontended poll: warp 0, lane L watches CTA L's flag (1 L2 line)
    if (tid < 32){
      unsigned vfl, target = (unsigned)(s + 1);
      do {
        asm volatile("ld.acquire.gpu.u32 %0, [%1];"
                     : "=r"(vfl) : "l"(&g_flag[grp][tid]));
      } while (__any_sync(0xffffffffu, vfl < target));
    }
    __syncthreads();
  }

  // final (h_T, c_T), appended after hidden_seq if the output carries them
  if (tid < 64 && out_size >= 16777216 + 16384){
    size_t base = (size_t)16777216 + (size_t)gb * 256 + j0 + uu;
    out[base]        = hlast;
    out[base + 8192] = cst;
  }
}

extern "C" void kernel_launch(void* const* d_in, const int* in_sizes, int n_in,
                              void* d_out, int out_size) {
  const float* x  = (const float*)d_in[0];
  const float* Wf = (const float*)d_in[1];
  const float* Uf = (const float*)d_in[2];
  const float* bf = (const float*)d_in[3];
  const float* Wi = (const float*)d_in[4];
  const float* Ui = (const float*)d_in[5];
  const float* bi = (const float*)d_in[6];
  const float* Wo = (const float*)d_in[7];
  const float* Uo = (const float*)d_in[8];
  const float* bo = (const float*)d_in[9];
  const float* Wc = (const float*)d_in[10];
  const float* Uc = (const float*)d_in[11];
  const float* bc = (const float*)d_in[12];
  float* out = (float*)d_out;

  init_state<<<64, 256>>>();
  dim3 g1(512, 16);
  xw_gemm<<<g1, 256>>>(x, Wf, Wi, Wc, Wo, bf, bi, bc, bo);
  lstm_rec<<<128, 256>>>(Uf, Ui, Uc, Uo, out, out_size);
}

// round 13
// speedup vs baseline: 3.3336x; 1.6837x over previous
#include <cuda_runtime.h>

typedef unsigned long long ull;

#define S_LEN 2048
#define COLS 1024

__device__ float g_xg[(size_t)32 * S_LEN * COLS];   // [b*S+s][gate*256+j], gates f,i,c,o

__device__ __forceinline__ ull fma2(ull a, ull b, ull c){
  ull d; asm("fma.rn.f32x2 %0, %1, %2, %3;" : "=l"(d) : "l"(a), "l"(b), "l"(c)); return d;
}
__device__ __forceinline__ ull dup2(float x){
  ull d; asm("mov.b64 %0, {%1, %1};" : "=l"(d) : "f"(x)); return d;
}
__device__ __forceinline__ ull pack2(float lo, float hi){
  ull d; asm("mov.b64 %0, {%1, %2};" : "=l"(d) : "f"(lo), "f"(hi)); return d;
}
__device__ __forceinline__ void unpack2(ull v, float& lo, float& hi){
  asm("mov.b64 {%0, %1}, %2;" : "=f"(lo), "=f"(hi) : "l"(v));
}
__device__ __forceinline__ float sigmoidf_(float x){ return 1.f / (1.f + __expf(-x)); }
__device__ __forceinline__ unsigned smem_u32(const void* p){
  unsigned a; asm("{ .reg .u64 t; cvta.to.shared.u64 t, %1; cvt.u32.u64 %0, t; }" : "=r"(a) : "l"(p));
  return a;
}
__device__ __forceinline__ void st_cluster_f32(unsigned laddr, unsigned rank, float v){
  asm volatile("{ .reg .b32 ra; mapa.shared::cluster.u32 ra, %0, %1; "
               "st.shared::cluster.f32 [ra], %2; }" :: "r"(laddr), "r"(rank), "f"(v) : "memory");
}

// ---------------- kernel 1: xg = x @ W + b (fp32x2 GEMM, 128x64x32 tiles) ----------------
__global__ __launch_bounds__(256, 2) void xw_gemm(
    const float* __restrict__ x,
    const float* __restrict__ Wf, const float* __restrict__ Wi,
    const float* __restrict__ Wc, const float* __restrict__ Wo,
    const float* __restrict__ bf, const float* __restrict__ bi,
    const float* __restrict__ bc, const float* __restrict__ bo)
{
  __shared__ float A_s[32][132];
  __shared__ float B_s[32][68];
  const int r0 = blockIdx.x * 128;
  const int c0 = blockIdx.y * 64;
  const int gate = c0 >> 8, j0 = c0 & 255;
  const float* Wg; const float* bg;
  if (gate == 0){ Wg = Wf; bg = bf; } else if (gate == 1){ Wg = Wi; bg = bi; }
  else if (gate == 2){ Wg = Wc; bg = bc; } else { Wg = Wo; bg = bo; }

  const int tid = threadIdx.x;
  const int tx = tid & 15, ty = tid >> 4;
  const int arow = tid >> 3, ak = (tid & 7) * 4;

  ull acc[4][4];
  #pragma unroll
  for (int i = 0; i < 4; i++)
    #pragma unroll
    for (int j = 0; j < 4; j++) acc[i][j] = 0ull;

  for (int kc = 0; kc < 256; kc += 32){
    #pragma unroll
    for (int i = 0; i < 4; i++){
      float4 v = *(const float4*)&x[(size_t)(r0 + arow + i*32) * 256 + kc + ak];
      A_s[ak+0][arow + i*32] = v.x; A_s[ak+1][arow + i*32] = v.y;
      A_s[ak+2][arow + i*32] = v.z; A_s[ak+3][arow + i*32] = v.w;
    }
    #pragma unroll
    for (int j = 0; j < 2; j++){
      int e = tid + j*256, kk = e >> 4, nn = (e & 15) * 4;
      *(float4*)&B_s[kk][nn] = *(const float4*)&Wg[(size_t)(kc + kk) * 256 + j0 + nn];
    }
    __syncthreads();
    #pragma unroll
    for (int k = 0; k < 32; k++){
      ulonglong2 a01 = *(const ulonglong2*)&A_s[k][ty*8];
      ulonglong2 a23 = *(const ulonglong2*)&A_s[k][ty*8 + 4];
      float4 bq = *(const float4*)&B_s[k][tx*4];
      ull bb0 = dup2(bq.x), bb1 = dup2(bq.y), bb2 = dup2(bq.z), bb3 = dup2(bq.w);
      ull av[4] = {a01.x, a01.y, a23.x, a23.y};
      #pragma unroll
      for (int i = 0; i < 4; i++){
        acc[i][0] = fma2(av[i], bb0, acc[i][0]);
        acc[i][1] = fma2(av[i], bb1, acc[i][1]);
        acc[i][2] = fma2(av[i], bb2, acc[i][2]);
        acc[i][3] = fma2(av[i], bb3, acc[i][3]);
      }
    }
    __syncthreads();
  }

  float bias[4];
  #pragma unroll
  for (int j = 0; j < 4; j++) bias[j] = bg[j0 + tx*4 + j];
  #pragma unroll
  for (int i = 0; i < 4; i++){
    float lo[4], hi[4];
    #pragma unroll
    for (int j = 0; j < 4; j++) unpack2(acc[i][j], lo[j], hi[j]);
    size_t base = (size_t)(r0 + ty*8 + 2*i) * COLS + c0 + tx*4;
    *(float4*)&g_xg[base]        = make_float4(lo[0]+bias[0], lo[1]+bias[1], lo[2]+bias[2], lo[3]+bias[3]);
    *(float4*)&g_xg[base + COLS] = make_float4(hi[0]+bias[0], hi[1]+bias[1], hi[2]+bias[2], hi[3]+bias[3]);
  }
}

// ---------------- kernel 2: clustered recurrence ----------------
// 128 CTAs = 16 groups (2 batches each) x 8-CTA clusters. CTA owns units
// [r*32, r*32+32) for all 4 gates; U slice register-resident (64 ull/thread).
// h exchanged via DSMEM push + hardware cluster barrier. No L2 state at all.
__global__ __launch_bounds__(256, 1) __cluster_dims__(8, 1, 1)
void lstm_rec(
    const float* __restrict__ Uf, const float* __restrict__ Ui,
    const float* __restrict__ Uc, const float* __restrict__ Uo,
    float* __restrict__ out, int out_size)
{
  __shared__ float h_s[2][2][256];   // [phase][batch][k]
  __shared__ float red[8 * 256];     // [k-slice][ (g*32+u)*2 + b ]

  const int tid = threadIdx.x;
  const int w = tid >> 5, lane = tid & 31;
  const int r   = blockIdx.x & 7;    // cluster rank
  const int grp = blockIdx.x >> 3;   // 0..15
  const int ju  = r * 32 + lane;     // this thread's global unit (col within gate)
  const int kb  = w * 32;            // this thread's k-chunk

  // U slice -> registers: ur[gate][jj] covers k in [kb+4jj, kb+4jj+4), col ju
  ulonglong2 ur[4][8];
  #pragma unroll
  for (int g = 0; g < 4; g++){
    const float* Ug = (g == 0) ? Uf : (g == 1) ? Ui : (g == 2) ? Uc : Uo;
    #pragma unroll
    for (int jj = 0; jj < 8; jj++){
      int k0 = kb + jj * 4;
      float a0 = __ldg(&Ug[(size_t)(k0 + 0) * 256 + ju]);
      float a1 = __ldg(&Ug[(size_t)(k0 + 1) * 256 + ju]);
      float a2 = __ldg(&Ug[(size_t)(k0 + 2) * 256 + ju]);
      float a3 = __ldg(&Ug[(size_t)(k0 + 3) * 256 + ju]);
      ur[g][jj].x = pack2(a0, a1);
      ur[g][jj].y = pack2(a2, a3);
    }
  }

  // zero both h buffers, then sync cluster before anyone can push
  for (int e = tid; e < 2 * 2 * 256; e += 256) ((float*)h_s)[e] = 0.f;
  __syncthreads();
  asm volatile("barrier.cluster.arrive.aligned;" ::: "memory");

  const unsigned hs_base = smem_u32(h_s);
  const int b_g = tid >> 5;                 // gate-thread batch (tid<64: warp0 b0, warp1 b1)
  const int gb = grp * 2 + b_g;
  float cst = 0.f, hlast = 0.f;

  for (int s = 0; s < S_LEN; s++){
    const int p = s & 1, pn = p ^ 1;

    // xg prefetch: issue before the cluster wait so DRAM latency overlaps it
    float xg0, xg1, xg2, xg3;
    if (tid < 64){
      const float* xp = &g_xg[((size_t)gb * S_LEN + s) * COLS + ju];
      xg0 = __ldg(xp); xg1 = __ldg(xp + 256); xg2 = __ldg(xp + 512); xg3 = __ldg(xp + 768);
    }
    asm volatile("barrier.cluster.wait.aligned;" ::: "memory");

    // matvec: 128 fma2/thread, h via broadcast LDS.128, U in registers
    ull acc[4][2];
    #pragma unroll
    for (int g = 0; g < 4; g++){ acc[g][0] = 0ull; acc[g][1] = 0ull; }
    #pragma unroll
    for (int jj = 0; jj < 8; jj++){
      ulonglong2 h0 = *(const ulonglong2*)&h_s[p][0][kb + jj*4];
      ulonglong2 h1 = *(const ulonglong2*)&h_s[p][1][kb + jj*4];
      #pragma unroll
      for (int g = 0; g < 4; g++){
        acc[g][0] = fma2(h0.x, ur[g][jj].x, acc[g][0]);
        acc[g][0] = fma2(h0.y, ur[g][jj].y, acc[g][0]);
        acc[g][1] = fma2(h1.x, ur[g][jj].x, acc[g][1]);
        acc[g][1] = fma2(h1.y, ur[g][jj].y, acc[g][1]);
      }
    }
    #pragma unroll
    for (int g = 0; g < 4; g++){
      float l0, u0, l1, u1;
      unpack2(acc[g][0], l0, u0);
      unpack2(acc[g][1], l1, u1);
      *(float2*)&red[w*256 + (g*32 + lane)*2] = make_float2(l0 + u0, l1 + u1);
    }
    __syncthreads();

    // gates: tid<64 = (batch b_g, unit lane)
    if (tid < 64){
      float z0 = xg0, z1 = xg1, z2 = xg2, z3 = xg3;
      #pragma unroll
      for (int ww = 0; ww < 8; ww++){
        int base = ww*256 + lane*2 + b_g;
        z0 += red[base +   0];
        z1 += red[base +  64];
        z2 += red[base + 128];
        z3 += red[base + 192];
      }
      float f  = sigmoidf_(z0);
      float ii = sigmoidf_(z1);
      float gg = tanhf(z2);
      float oo = sigmoidf_(z3);
      cst = f * cst + ii * gg;
      hlast = oo * tanhf(cst);
      // push h into every cluster CTA's h_s[pn][b_g][ju]
      unsigned haddr = hs_base + (unsigned)(((pn*2 + b_g)*256 + ju) * 4);
      #pragma unroll
      for (int t = 0; t < 8; t++) st_cluster_f32(haddr, (unsigned)t, hlast);
      out[((size_t)gb * S_LEN + s) * 256 + ju] = hlast;
    }
    asm volatile("barrier.cluster.arrive.aligned;" ::: "memory");
  }
  asm volatile("barrier.cluster.wait.aligned;" ::: "memory");

  // final (h_T, c_T), appended after hidden_seq if the output carries them
  if (tid < 64 && out_size >= 16777216 + 16384){
    size_t base = (size_t)16777216 + (size_t)gb * 256 + ju;
    out[base]        = hlast;
    out[base + 8192] = cst;
  }
}

extern "C" void kernel_launch(void* const* d_in, const int* in_sizes, int n_in,
                              void* d_out, int out_size) {
  const float* x  = (const float*)d_in[0];
  const float* Wf = (const float*)d_in[1];
  const float* Uf = (const float*)d_in[2];
  const float* bf = (const float*)d_in[3];
  const float* Wi = (const float*)d_in[4];
  const float* Ui = (const float*)d_in[5];
  const float* bi = (const float*)d_in[6];
  const float* Wo = (const float*)d_in[7];
  const float* Uo = (const float*)d_in[8];
  const float* bo = (const float*)d_in[9];
  const float* Wc = (const float*)d_in[10];
  const float* Uc = (const float*)d_in[11];
  const float* bc = (const float*)d_in[12];
  float* out = (float*)d_out;

  dim3 g1(512, 16);
  xw_gemm<<<g1, 256>>>(x, Wf, Wi, Wc, Wo, bf, bi, bc, bo);
  lstm_rec<<<128, 256>>>(Uf, Ui, Uc, Uo, out, out_size);
}